// round 14
// baseline (speedup 1.0000x reference)
#include <cuda_runtime.h>
#include <cuda_fp16.h>
#include <cstdint>
#include <cstddef>

typedef __half f16;

#define T_ 256
#define B_ 64
#define D_ 512
#define H_ 1024
#define G_ 4096
#define TB_ (T_ * B_)
#define OUTS_ (TB_ * H_)
#define NB_ 128          // merged-role CTAs (scheduled first)
#define G0B_ 4096        // G0-role CTAs

// ---------------- device scratch ----------------
__device__ f16   g_Xp  [(size_t)TB_ * D_];
__device__ f16   g_Wi0p[(size_t)G_  * D_];
__device__ f16   g_Wh0p[(size_t)G_  * H_];
__device__ f16   g_Wi1p[(size_t)G_  * H_];
__device__ f16   g_Wh1p[(size_t)G_  * H_];
__device__ float g_b0[G_], g_b1[G_];
__device__ float g_G0[(size_t)TB_ * G_];
__device__ float g_c0s[2 * B_ * H_];
__device__ f16   g_h0p[2][B_ * H_];
__device__ f16   g_h1p[2][B_ * H_];
__device__ unsigned g_bar_grp0[8], g_bar_root0, g_gen0;   // tail0 barrier (reset in setup)
__device__ unsigned g_bar_grp1[8], g_bar_root1, g_gen1;   // tail1 barrier
__device__ unsigned g_g0_done[128];                        // G0 row-tile counters

// ---------------- helpers ----------------
__device__ __forceinline__ void cp_async16(void* sdst, const void* gsrc) {
    uint32_t s = (uint32_t)__cvta_generic_to_shared(sdst);
    asm volatile("cp.async.cg.shared.global [%0], [%1], 16;\n" :: "r"(s), "l"(gsrc));
}
__device__ __forceinline__ void cp_commit() { asm volatile("cp.async.commit_group;\n"); }
template <int N> __device__ __forceinline__ void cp_wait() {
    asm volatile("cp.async.wait_group %0;\n" :: "n"(N));
}
__device__ __forceinline__ unsigned ld_acq(const unsigned* p) {
    unsigned v; asm volatile("ld.acquire.gpu.u32 %0, [%1];" : "=r"(v) : "l"(p)); return v;
}
__device__ __forceinline__ void mma16816(float* d,
    uint32_t a0, uint32_t a1, uint32_t a2, uint32_t a3, uint32_t b0, uint32_t b1)
{
    asm volatile(
        "mma.sync.aligned.m16n8k16.row.col.f32.f16.f16.f32 "
        "{%0,%1,%2,%3},{%4,%5,%6,%7},{%8,%9},{%0,%1,%2,%3};\n"
        : "+f"(d[0]), "+f"(d[1]), "+f"(d[2]), "+f"(d[3])
        : "r"(a0), "r"(a1), "r"(a2), "r"(a3), "r"(b0), "r"(b1));
}
__device__ __forceinline__ void ldsm4(uint32_t& a, uint32_t& b, uint32_t& c, uint32_t& d,
                                      uint32_t addr)
{
    asm volatile("ldmatrix.sync.aligned.m8n8.x4.shared.b16 {%0,%1,%2,%3}, [%4];"
        : "=r"(a), "=r"(b), "=r"(c), "=r"(d) : "r"(addr));
}
__device__ __forceinline__ float sigmoidf_(float z) {
    return __fdividef(1.f, 1.f + __expf(-z));
}
__device__ __forceinline__ float tanhf_(float z) {
    return __fdividef(2.f, 1.f + __expf(-2.f * z)) - 1.f;
}

// ---------------- unified setup kernel ----------------
__global__ void setup_kernel(const float* __restrict__ input,
                             const float* __restrict__ h0, const float* __restrict__ c0,
                             const float* __restrict__ Wi0, const float* __restrict__ Wh0,
                             const float* __restrict__ bi0, const float* __restrict__ bh0,
                             const float* __restrict__ Wi1, const float* __restrict__ Wh1,
                             const float* __restrict__ bi1, const float* __restrict__ bh1)
{
    int blk = blockIdx.x;
    int tid = threadIdx.x;

    if (blk < 1792) {
        const float* src; f16* dst; int K, base_blk, nblk;
        if (blk < 256)       { src = Wi0; dst = g_Wi0p; K = D_; base_blk = 0;    nblk = 256; }
        else if (blk < 768)  { src = Wh0; dst = g_Wh0p; K = H_; base_blk = 256;  nblk = 512; }
        else if (blk < 1280) { src = Wi1; dst = g_Wi1p; K = H_; base_blk = 768;  nblk = 512; }
        else                 { src = Wh1; dst = g_Wh1p; K = H_; base_blk = 1280; nblk = 512; }
        int K4 = K >> 2;
        int total = G_ * K4;
        for (int id = (blk - base_blk) * 256 + tid; id < total; id += nblk * 256) {
            int r = id / K4, k4 = (id - r * K4) * 4;
            int sr = (r & 3) * H_ + (r >> 2);
            float4 v = *(const float4*)&src[(size_t)sr * K + k4];
            __half2 a = {__float2half_rn(v.x), __float2half_rn(v.y)};
            __half2 b = {__float2half_rn(v.z), __float2half_rn(v.w)};
            *(uint2*)&dst[(size_t)r * K + k4] = make_uint2(*(uint32_t*)&a, *(uint32_t*)&b);
        }
    } else if (blk < 2816) {
        int total = TB_ * (D_ >> 2);
        for (int id = (blk - 1792) * 256 + tid; id < total; id += 1024 * 256) {
            int r = id / (D_ >> 2), k4 = (id - r * (D_ >> 2)) * 4;
            float4 v = *(const float4*)&input[(size_t)r * D_ + k4];
            __half2 a = {__float2half_rn(v.x), __float2half_rn(v.y)};
            __half2 b = {__float2half_rn(v.z), __float2half_rn(v.w)};
            *(uint2*)&g_Xp[(size_t)r * D_ + k4] = make_uint2(*(uint32_t*)&a, *(uint32_t*)&b);
        }
    } else if (blk < 2832) {
        int r = (blk - 2816) * 256 + tid;
        if (r < 128) g_g0_done[r] = 0u;
        if (r < 8) { g_bar_grp0[r] = 0u; g_bar_grp1[r] = 0u; }
        if (r == 8) { g_bar_root0 = 0u; g_bar_root1 = 0u; g_gen0 = 0u; g_gen1 = 0u; }
        if (r < G_) {
            int sr = (r & 3) * H_ + (r >> 2);
            g_b0[r] = bi0[sr] + bh0[sr];
            g_b1[r] = bi1[sr] + bh1[sr];
        }
    } else {
        for (int id = (blk - 2832) * 256 + tid; id < 2 * B_ * H_; id += 16 * 256) {
            int l = id / (B_ * H_);
            int b = (id / H_) % B_;
            int j = id % H_;
            float hv = h0[(b * 2 + l) * H_ + j];
            g_c0s[id] = c0[(b * 2 + l) * H_ + j];
            f16 hh = __float2half_rn(hv);
            if (l == 0) g_h0p[0][b * H_ + j] = hh;
            else        g_h1p[0][b * H_ + j] = hh;
        }
    }
}

// ---------------- G0-role body ----------------
#define GAS 72
__device__ void g0_body(int gid, char* smraw)
{
    f16* sm = (f16*)smraw;
    const int AS = 128 * GAS;
    f16* sA = sm;
    f16* sB = sm + 3 * AS;
    uint32_t sA_u = (uint32_t)__cvta_generic_to_shared(sA);
    uint32_t sB_u = (uint32_t)__cvta_generic_to_shared(sB);

    const f16 *A = g_Xp, *B = g_Wi0p;
    const int K = 512;
    int by = gid >> 5, bx = gid & 31;
    int m0 = by * 128, n0 = bx * 128;

    int tid = threadIdx.x, w = tid >> 5, lane = tid & 31, g = lane >> 2, t4 = lane & 3;
    int wm = w & 1, wn = w >> 1;
    const int NC = K / 64;

    int lr = lane & 15;
    int lcA = (lane >> 4) * 8;
    uint32_t aBase[4], bBase[2];
#pragma unroll
    for (int mt = 0; mt < 4; mt++)
        aBase[mt] = (uint32_t)(((wm * 64 + mt * 16 + lr) * GAS + lcA) * 2);
#pragma unroll
    for (int p = 0; p < 2; p++)
        bBase[p] = (uint32_t)(((wn * 32 + p * 16 + (lane & 7) + ((lane >> 4) & 1) * 8) * GAS
                               + ((lane >> 3) & 1) * 8) * 2);

    float acc[4][4][4];
#pragma unroll
    for (int a = 0; a < 4; a++)
#pragma unroll
        for (int b = 0; b < 4; b++)
#pragma unroll
            for (int c = 0; c < 4; c++) acc[a][b][c] = 0.f;

    auto issue = [&](int c) {
        int k0 = c * 64;
        int st = c % 3;
#pragma unroll
        for (int v = 0; v < 4; v++) {
            int idx = tid + v * 256;
            int r = idx >> 3, s = idx & 7;
            cp_async16(&sA[st * AS + r * GAS + s * 8], &A[(size_t)(m0 + r) * K + k0 + s * 8]);
        }
#pragma unroll
        for (int v = 0; v < 4; v++) {
            int idx = tid + v * 256;
            int r = idx >> 3, s = idx & 7;
            cp_async16(&sB[st * AS + r * GAS + s * 8], &B[(size_t)(n0 + r) * K + k0 + s * 8]);
        }
        cp_commit();
    };

    issue(0); issue(1);
    for (int c = 0; c < NC; c++) {
        if (c + 1 < NC) cp_wait<1>(); else cp_wait<0>();
        __syncthreads();
        if (c + 2 < NC) issue(c + 2);
        uint32_t stA = sA_u + (uint32_t)((c % 3) * AS * 2);
        uint32_t stB = sB_u + (uint32_t)((c % 3) * AS * 2);
#pragma unroll
        for (int kk = 0; kk < 4; kk++) {
            uint32_t kbb = (uint32_t)(kk * 32);
            uint32_t Aa[4][4], Bh[4][2];
#pragma unroll
            for (int mt = 0; mt < 4; mt++)
                ldsm4(Aa[mt][0], Aa[mt][1], Aa[mt][2], Aa[mt][3], stA + aBase[mt] + kbb);
#pragma unroll
            for (int p = 0; p < 2; p++)
                ldsm4(Bh[2 * p][0], Bh[2 * p][1], Bh[2 * p + 1][0], Bh[2 * p + 1][1],
                      stB + bBase[p] + kbb);
#pragma unroll
            for (int mt = 0; mt < 4; mt++)
#pragma unroll
                for (int nt = 0; nt < 4; nt++)
                    mma16816(acc[mt][nt], Aa[mt][0], Aa[mt][1], Aa[mt][2], Aa[mt][3], Bh[nt][0], Bh[nt][1]);
        }
    }

#pragma unroll
    for (int mt = 0; mt < 4; mt++)
#pragma unroll
        for (int nt = 0; nt < 4; nt++) {
            int row = m0 + wm * 64 + mt * 16 + g;
            int col = n0 + wn * 32 + nt * 8 + 2 * t4;
            float ba = g_b0[col], bb = g_b0[col + 1];
            *(float2*)&g_G0[(size_t)row * G_ + col] =
                make_float2(acc[mt][nt][0] + ba, acc[mt][nt][1] + bb);
            *(float2*)&g_G0[(size_t)(row + 8) * G_ + col] =
                make_float2(acc[mt][nt][2] + ba, acc[mt][nt][3] + bb);
        }

    __threadfence();
    __syncthreads();
    if (tid == 0) atomicAdd(&g_g0_done[by], 1u);
}

// ---------------- merged-role body (wavefront, split barriers) ----------------
#define WSTR 1032
#define ASTR 136
#define ASTG (64 * ASTR)
#define BSTG (32 * ASTR)
#define ZBANK (64 * 36)
#define MERGED_SMEM ((64 * WSTR + 3 * ASTG + 3 * BSTG) * 2 + 2 * ZBANK * 4)   // 228864 B

__device__ void merged_body(int rbid, const int* __restrict__ reset,
                            float* __restrict__ out, char* smraw)
{
    f16* smem = (f16*)smraw;
    f16* sW0 = smem;
    f16* sW1 = smem + 32 * WSTR;
    f16* sA  = smem + 64 * WSTR;
    f16* sB  = sA + 3 * ASTG;
    float* zs = (float*)(sB + 3 * BSTG);
    uint32_t sW0_u = (uint32_t)__cvta_generic_to_shared(sW0);
    uint32_t sW1_u = (uint32_t)__cvta_generic_to_shared(sW1);
    uint32_t sA_u  = (uint32_t)__cvta_generic_to_shared(sA);
    uint32_t sB_u  = (uint32_t)__cvta_generic_to_shared(sB);

    int tid = threadIdx.x, w = tid >> 5, lane = tid & 31, g = lane >> 2, t4 = lane & 3;
    int wk = w & 1, wn = (w >> 1) & 1, wm = w >> 2;
    int n0 = rbid * 32;

    for (int i = tid; i < 32 * 128; i += 256) {
        int r = i >> 7, sseg = i & 127;
        *(uint4*)&sW0[r * WSTR + sseg * 8] = *(const uint4*)&g_Wh0p[(size_t)(n0 + r) * H_ + sseg * 8];
        *(uint4*)&sW1[r * WSTR + sseg * 8] = *(const uint4*)&g_Wh1p[(size_t)(n0 + r) * H_ + sseg * 8];
    }

    int lr = lane & 15;
    int lcA = (lane >> 4) * 8;
    uint32_t aBase[2];
    aBase[0] = (uint32_t)(((wm * 32 + 0 + lr) * ASTR + lcA) * 2);
    aBase[1] = (uint32_t)(((wm * 32 + 16 + lr) * ASTR + lcA) * 2);
    uint32_t wBase[2], bBaseS[2];
#pragma unroll
    for (int nt = 0; nt < 2; nt++) {
        wBase[nt]  = (uint32_t)(((wn * 16 + nt * 8 + (lane & 7)) * WSTR
                                 + ((lane >> 3) & 1) * 8 + ((lane >> 4) & 1) * 16) * 2);
        bBaseS[nt] = (uint32_t)(((wn * 16 + nt * 8 + (lane & 7)) * ASTR
                                 + ((lane >> 3) & 1) * 8 + ((lane >> 4) & 1) * 16) * 2);
    }

    int bb = tid >> 3, jl = tid & 7, j = rbid * 8 + jl;
    int bb2 = (tid + 256) >> 3;
    int wrow[4] = { wm * 32 + g, wm * 32 + 8 + g, wm * 32 + 16 + g, wm * 32 + 24 + g };

    float c0r[2], c1r[2];
    c0r[0] = g_c0s[(0 * B_ + bb) * H_ + j];
    c0r[1] = g_c0s[(0 * B_ + bb2) * H_ + j];
    c1r[0] = g_c0s[(1 * B_ + bb) * H_ + j];
    c1r[1] = g_c0s[(1 * B_ + bb2) * H_ + j];

    float4 b1v = *(const float4*)&g_b1[n0 + 4 * jl];

    float rst0[2], rst1[2], kw[4];
    rst0[0] = (float)reset[bb];
    rst0[1] = (float)reset[bb2];
    rst1[0] = rst1[1] = 0.f;
    kw[0] = kw[1] = kw[2] = kw[3] = 1.f;

    // wait for G0 row-tile 0, then initial gp
    if (tid == 0) { while (ld_acq(&g_g0_done[0]) < 32u) { } }
    __syncthreads();
    float4 gp[2];
    gp[0] = __ldcs((const float4*)&g_G0[(size_t)bb * G_ + n0 + 4 * jl]);
    gp[1] = __ldcs((const float4*)&g_G0[(size_t)bb2 * G_ + n0 + 4 * jl]);

    unsigned grp = (unsigned)rbid >> 4;

    for (int s = 0; s <= T_; s++) {
        const f16* A0 = g_h0p[s & 1];          // h0_{s-1}
        const f16* A1 = g_h1p[(s + 1) & 1];    // h1_{s-2}

        // ---- wait bar0(s-1): all h0_{s-1} stores visible ----
        if (s >= 1) {
            if (tid == 0) { while (ld_acq(&g_gen0) < (unsigned)s) { } }
            __syncthreads();
        }

        float acc0[2][2][4], accWi[2][2][4];
#pragma unroll
        for (int a = 0; a < 2; a++)
#pragma unroll
            for (int b = 0; b < 2; b++)
#pragma unroll
                for (int c = 0; c < 4; c++) { acc0[a][b][c] = 0.f; accWi[a][b][c] = 0.f; }

        auto issueF = [&](int c) {
            int k0 = c * 128, st = c % 3;
#pragma unroll
            for (int v = 0; v < 4; v++) {
                int idx = tid + v * 256;
                int r = idx >> 4, sseg = idx & 15;
                cp_async16(&sA[st * ASTG + r * ASTR + sseg * 8], &A0[(size_t)r * H_ + k0 + sseg * 8]);
            }
#pragma unroll
            for (int v = 0; v < 2; v++) {
                int idx = tid + v * 256;
                int r = idx >> 4, sseg = idx & 15;
                cp_async16(&sB[st * BSTG + r * ASTR + sseg * 8],
                           &g_Wi1p[(size_t)(n0 + r) * H_ + k0 + sseg * 8]);
            }
            cp_commit();
        };
        auto issueH = [&](int c) {
            int k0 = c * 128, st = c % 3;
#pragma unroll
            for (int v = 0; v < 4; v++) {
                int idx = tid + v * 256;
                int r = idx >> 4, sseg = idx & 15;
                cp_async16(&sA[st * ASTG + r * ASTR + sseg * 8], &A1[(size_t)r * H_ + k0 + sseg * 8]);
            }
            cp_commit();
        };

        // ---- loop1: acc0 (Wh0) + accWi (Wi1), A = h0_{s-1} ----
        issueF(0); issueF(1);
        for (int c = 0; c < 8; c++) {
            if (c + 1 < 8) cp_wait<1>(); else cp_wait<0>();
            __syncthreads();
            if (c + 2 < 8) issueF(c + 2);
            uint32_t stA = sA_u + (uint32_t)((c % 3) * ASTG * 2);
            uint32_t stB = sB_u + (uint32_t)((c % 3) * BSTG * 2);
            uint32_t wOffC = (uint32_t)(c * 128 * 2);
#pragma unroll
            for (int kpi = 0; kpi < 2; kpi++) {
                int kp = kpi * 2 + wk;
                uint32_t kpb = (uint32_t)(kp * 64);
                uint32_t Bq0[2][4], BqW[2][4];
#pragma unroll
                for (int nt = 0; nt < 2; nt++) {
                    ldsm4(Bq0[nt][0], Bq0[nt][1], Bq0[nt][2], Bq0[nt][3],
                          sW0_u + wBase[nt] + wOffC + kpb);
                    ldsm4(BqW[nt][0], BqW[nt][1], BqW[nt][2], BqW[nt][3],
                          stB + bBaseS[nt] + kpb);
                }
#pragma unroll
                for (int h = 0; h < 2; h++) {
                    uint32_t kbb = kpb + (uint32_t)(h * 32);
                    uint32_t Aa[2][4];
#pragma unroll
                    for (int mt = 0; mt < 2; mt++)
                        ldsm4(Aa[mt][0], Aa[mt][1], Aa[mt][2], Aa[mt][3], stA + aBase[mt] + kbb);
#pragma unroll
                    for (int mt = 0; mt < 2; mt++)
#pragma unroll
                        for (int nt = 0; nt < 2; nt++) {
                            mma16816(acc0[mt][nt], Aa[mt][0], Aa[mt][1], Aa[mt][2], Aa[mt][3],
                                     Bq0[nt][h * 2], Bq0[nt][h * 2 + 1]);
                            mma16816(accWi[mt][nt], Aa[mt][0], Aa[mt][1], Aa[mt][2], Aa[mt][3],
                                     BqW[nt][h * 2], BqW[nt][h * 2 + 1]);
                        }
                }
            }
        }

        // layer0 partials -> zs
        {
            float* zb = zs + wk * ZBANK;
#pragma unroll
            for (int mt = 0; mt < 2; mt++)
#pragma unroll
                for (int nt = 0; nt < 2; nt++) {
                    int r0 = wm * 32 + mt * 16 + g;
                    int c0 = wn * 16 + nt * 8 + 2 * t4;
                    zb[r0 * 36 + c0]     = acc0[mt][nt][0];
                    zb[r0 * 36 + c0 + 1] = acc0[mt][nt][1];
                    zb[(r0 + 8) * 36 + c0]     = acc0[mt][nt][2];
                    zb[(r0 + 8) * 36 + c0 + 1] = acc0[mt][nt][3];
                }
        }
        __syncthreads();

        // ---- tail0: layer0 activation, store h0_s ----
        if (s < T_) {
#pragma unroll
            for (int it = 0; it < 2; it++) {
                int b = it ? bb2 : bb;
                float keep = 1.0f - rst0[it];
                int zi_i = b * 36 + 4 * jl;
                float zi = gp[it].x + keep * (zs[zi_i + 0] + zs[ZBANK + zi_i + 0]);
                float zf = gp[it].y + keep * (zs[zi_i + 1] + zs[ZBANK + zi_i + 1]);
                float zg = gp[it].z + keep * (zs[zi_i + 2] + zs[ZBANK + zi_i + 2]);
                float zo = gp[it].w + keep * (zs[zi_i + 3] + zs[ZBANK + zi_i + 3]);
                float cn = sigmoidf_(zf) * keep * c0r[it] + sigmoidf_(zi) * tanhf_(zg);
                float hn = sigmoidf_(zo) * tanhf_(cn);
                c0r[it] = cn;
                g_h0p[(s + 1) & 1][b * H_ + j] = __float2half_rn(hn);
                if (s == T_ - 1) {
                    out[OUTS_ + (b * 2 + 0) * H_ + j] = hn;
                    out[OUTS_ + 2 * B_ * H_ + (b * 2 + 0) * H_ + j] = cn;
                }
            }
        }
        __syncthreads();
        // arrive bar0(s)
        if (s < T_ && tid == 0) {
            __threadfence();
            if (atomicAdd(&g_bar_grp0[grp], 1u) == 15u) {
                g_bar_grp0[grp] = 0u;
                if (atomicAdd(&g_bar_root0, 1u) == 7u) {
                    g_bar_root0 = 0u;
                    __threadfence();
                    g_gen0 = (unsigned)(s + 1);
                }
            }
        }

        // ---- wait bar1(s-1): all h1_{s-2} stores visible; + G0 producer gate ----
        if (tid == 0) {
            if (s >= 2) { while (ld_acq(&g_gen1) < (unsigned)(s - 1)) { } }
            if (s + 1 < T_) {
                unsigned by2 = (unsigned)(s + 1) >> 1;
                while (ld_acq(&g_g0_done[by2]) < 32u) { }
            }
        }
        __syncthreads();

        // gp prefetch for step s+1 (consumed at tail0(s+1))
        if (s + 1 < T_) {
            gp[0] = __ldcs((const float4*)&g_G0[((size_t)(s + 1) * B_ + bb) * G_ + n0 + 4 * jl]);
            gp[1] = __ldcs((const float4*)&g_G0[((size_t)(s + 1) * B_ + bb2) * G_ + n0 + 4 * jl]);
        }

        float hn_s[2], cn_s[2];
        if (s >= 1) {
            // ---- loop2: accWh (Wh1), A = h1_{s-2} ----
            float accWh[2][2][4];
#pragma unroll
            for (int a = 0; a < 2; a++)
#pragma unroll
                for (int b = 0; b < 2; b++)
#pragma unroll
                    for (int c = 0; c < 4; c++) accWh[a][b][c] = 0.f;

            issueH(0); issueH(1);
            for (int c = 0; c < 8; c++) {
                if (c + 1 < 8) cp_wait<1>(); else cp_wait<0>();
                __syncthreads();
                if (c + 2 < 8) issueH(c + 2);
                uint32_t stA = sA_u + (uint32_t)((c % 3) * ASTG * 2);
                uint32_t wOffC = (uint32_t)(c * 128 * 2);
#pragma unroll
                for (int kpi = 0; kpi < 2; kpi++) {
                    int kp = kpi * 2 + wk;
                    uint32_t kpb = (uint32_t)(kp * 64);
                    uint32_t Bq1[2][4];
#pragma unroll
                    for (int nt = 0; nt < 2; nt++)
                        ldsm4(Bq1[nt][0], Bq1[nt][1], Bq1[nt][2], Bq1[nt][3],
                              sW1_u + wBase[nt] + wOffC + kpb);
#pragma unroll
                    for (int h = 0; h < 2; h++) {
                        uint32_t kbb = kpb + (uint32_t)(h * 32);
                        uint32_t Aa[2][4];
#pragma unroll
                        for (int mt = 0; mt < 2; mt++)
                            ldsm4(Aa[mt][0], Aa[mt][1], Aa[mt][2], Aa[mt][3], stA + aBase[mt] + kbb);
#pragma unroll
                        for (int mt = 0; mt < 2; mt++)
#pragma unroll
                            for (int nt = 0; nt < 2; nt++)
                                mma16816(accWh[mt][nt], Aa[mt][0], Aa[mt][1], Aa[mt][2], Aa[mt][3],
                                         Bq1[nt][h * 2], Bq1[nt][h * 2 + 1]);
                    }
                }
            }

            {
                float* zb = zs + wk * ZBANK;
#pragma unroll
                for (int mt = 0; mt < 2; mt++)
#pragma unroll
                    for (int nt = 0; nt < 2; nt++) {
                        int r0 = wm * 32 + mt * 16 + g;
                        int c0 = wn * 16 + nt * 8 + 2 * t4;
                        float k0f = kw[mt * 2 + 0], k1f = kw[mt * 2 + 1];
                        zb[r0 * 36 + c0]     = k0f * accWh[mt][nt][0] + accWi[mt][nt][0];
                        zb[r0 * 36 + c0 + 1] = k0f * accWh[mt][nt][1] + accWi[mt][nt][1];
                        zb[(r0 + 8) * 36 + c0]     = k1f * accWh[mt][nt][2] + accWi[mt][nt][2];
                        zb[(r0 + 8) * 36 + c0 + 1] = k1f * accWh[mt][nt][3] + accWi[mt][nt][3];
                    }
            }
            __syncthreads();

            // ---- tail1: layer1 activation, store h1_{s-1} ----
#pragma unroll
            for (int it = 0; it < 2; it++) {
                int b = it ? bb2 : bb;
                float keep = 1.0f - rst1[it];
                int zi_i = b * 36 + 4 * jl;
                float zi = b1v.x + (zs[zi_i + 0] + zs[ZBANK + zi_i + 0]);
                float zf = b1v.y + (zs[zi_i + 1] + zs[ZBANK + zi_i + 1]);
                float zg = b1v.z + (zs[zi_i + 2] + zs[ZBANK + zi_i + 2]);
                float zo = b1v.w + (zs[zi_i + 3] + zs[ZBANK + zi_i + 3]);
                float cn = sigmoidf_(zf) * keep * c1r[it] + sigmoidf_(zi) * tanhf_(zg);
                float hn = sigmoidf_(zo) * tanhf_(cn);
                c1r[it] = cn; cn_s[it] = cn; hn_s[it] = hn;
                g_h1p[s & 1][b * H_ + j] = __float2half_rn(hn);
                if (s == T_) {
                    out[OUTS_ + (b * 2 + 1) * H_ + j] = hn;
                    out[OUTS_ + 2 * B_ * H_ + (b * 2 + 1) * H_ + j] = cn;
                }
            }
            __syncthreads();
            // arrive bar1(s)
            if (s < T_ && tid == 0) {
                __threadfence();
                if (atomicAdd(&g_bar_grp1[grp], 1u) == 15u) {
                    g_bar_grp1[grp] = 0u;
                    if (atomicAdd(&g_bar_root1, 1u) == 7u) {
                        g_bar_root1 = 0u;
                        __threadfence();
                        g_gen1 = (unsigned)s;
                    }
                }
            }
        }

        // ---- epilogue: output stores + reset/kw prefetch ----
        if (s >= 1) {
            int t1 = s - 1;
#pragma unroll
            for (int it = 0; it < 2; it++) {
                int b = it ? bb2 : bb;
                __stcs(&out[(size_t)t1 * B_ * H_ + b * H_ + j], hn_s[it]);
            }
        }
        if (s + 1 <= T_) {
            rst1[0] = rst0[0]; rst1[1] = rst0[1];
            if (s + 1 < T_) {
                rst0[0] = (float)reset[(s + 1) * B_ + bb];
                rst0[1] = (float)reset[(s + 1) * B_ + bb2];
            }
#pragma unroll
            for (int i = 0; i < 4; i++)
                kw[i] = 1.0f - (float)reset[s * B_ + wrow[i]];
        }
    }
}

// ---------------- fused kernel ----------------
__global__ __launch_bounds__(256, 1) void fused_kernel(const int* __restrict__ reset,
                                                       float* __restrict__ out)
{
    extern __shared__ char smraw[];
    int bid = blockIdx.x;
    if (bid < NB_) merged_body(bid, reset, out, smraw);
    else           g0_body(bid - NB_, smraw);
}

// ---------------- launch ----------------
extern "C" void kernel_launch(void* const* d_in, const int* in_sizes, int n_in,
                              void* d_out, int out_size)
{
    (void)in_sizes; (void)n_in; (void)out_size;
    const float* input = (const float*)d_in[0];
    const int*   reset = (const int*)d_in[1];
    const float* h0    = (const float*)d_in[2];
    const float* c0    = (const float*)d_in[3];
    const float* Wi0   = (const float*)d_in[4];
    const float* Wh0   = (const float*)d_in[5];
    const float* bi0   = (const float*)d_in[6];
    const float* bh0   = (const float*)d_in[7];
    const float* Wi1   = (const float*)d_in[8];
    const float* Wh1   = (const float*)d_in[9];
    const float* bi1   = (const float*)d_in[10];
    const float* bh1   = (const float*)d_in[11];
    float* out = (float*)d_out;

    cudaFuncSetAttribute(fused_kernel, cudaFuncAttributeMaxDynamicSharedMemorySize, MERGED_SMEM);

    setup_kernel<<<2848, 256>>>(input, h0, c0, Wi0, Wh0, bi0, bh0, Wi1, Wh1, bi1, bh1);
    fused_kernel<<<NB_ + G0B_, 256, MERGED_SMEM>>>(reset, out);
}

// round 15
// speedup vs baseline: 1.0529x; 1.0529x over previous
#include <cuda_runtime.h>
#include <cuda_fp16.h>
#include <cstdint>
#include <cstddef>

typedef __half f16;

#define T_ 256
#define B_ 64
#define D_ 512
#define H_ 1024
#define G_ 4096
#define TB_ (T_ * B_)
#define OUTS_ (TB_ * H_)
#define NB_ 128          // merged-role CTAs
#define G0B_ 4096        // G0-role CTAs
#define NT_ 512          // threads per CTA

// ---------------- device scratch ----------------
__device__ f16   g_Xp  [(size_t)TB_ * D_];
__device__ f16   g_Wi0p[(size_t)G_  * D_];
__device__ f16   g_Wh0p[(size_t)G_  * H_];
__device__ f16   g_Wi1p[(size_t)G_  * H_];
__device__ f16   g_Wh1p[(size_t)G_  * H_];
__device__ float g_b0[G_], g_b1[G_];
__device__ float g_G0[(size_t)TB_ * G_];
__device__ float g_c0s[2 * B_ * H_];
__device__ f16   g_h0p[2][B_ * H_];
__device__ f16   g_h1p[2][B_ * H_];
__device__ unsigned g_bar_grp[8];
__device__ unsigned g_bar_root;
__device__ unsigned g_bar_gen;       // monotonic across replays
__device__ unsigned g_g0_done[128];  // cleared in setup

// ---------------- helpers ----------------
__device__ __forceinline__ void cp_async16(void* sdst, const void* gsrc) {
    uint32_t s = (uint32_t)__cvta_generic_to_shared(sdst);
    asm volatile("cp.async.cg.shared.global [%0], [%1], 16;\n" :: "r"(s), "l"(gsrc));
}
__device__ __forceinline__ void cp_commit() { asm volatile("cp.async.commit_group;\n"); }
template <int N> __device__ __forceinline__ void cp_wait() {
    asm volatile("cp.async.wait_group %0;\n" :: "n"(N));
}
__device__ __forceinline__ unsigned ld_acq(const unsigned* p) {
    unsigned v; asm volatile("ld.acquire.gpu.u32 %0, [%1];" : "=r"(v) : "l"(p)); return v;
}
__device__ __forceinline__ void mma16816(float* d,
    uint32_t a0, uint32_t a1, uint32_t a2, uint32_t a3, uint32_t b0, uint32_t b1)
{
    asm volatile(
        "mma.sync.aligned.m16n8k16.row.col.f32.f16.f16.f32 "
        "{%0,%1,%2,%3},{%4,%5,%6,%7},{%8,%9},{%0,%1,%2,%3};\n"
        : "+f"(d[0]), "+f"(d[1]), "+f"(d[2]), "+f"(d[3])
        : "r"(a0), "r"(a1), "r"(a2), "r"(a3), "r"(b0), "r"(b1));
}
__device__ __forceinline__ void ldsm4(uint32_t& a, uint32_t& b, uint32_t& c, uint32_t& d,
                                      uint32_t addr)
{
    asm volatile("ldmatrix.sync.aligned.m8n8.x4.shared.b16 {%0,%1,%2,%3}, [%4];"
        : "=r"(a), "=r"(b), "=r"(c), "=r"(d) : "r"(addr));
}
__device__ __forceinline__ float sigmoidf_(float z) {
    return __fdividef(1.f, 1.f + __expf(-z));
}
__device__ __forceinline__ float tanhf_(float z) {
    return __fdividef(2.f, 1.f + __expf(-2.f * z)) - 1.f;
}

// ---------------- unified setup kernel (256 threads) ----------------
__global__ void setup_kernel(const float* __restrict__ input,
                             const float* __restrict__ h0, const float* __restrict__ c0,
                             const float* __restrict__ Wi0, const float* __restrict__ Wh0,
                             const float* __restrict__ bi0, const float* __restrict__ bh0,
                             const float* __restrict__ Wi1, const float* __restrict__ Wh1,
                             const float* __restrict__ bi1, const float* __restrict__ bh1)
{
    int blk = blockIdx.x;
    int tid = threadIdx.x;

    if (blk < 1792) {
        const float* src; f16* dst; int K, base_blk, nblk;
        if (blk < 256)       { src = Wi0; dst = g_Wi0p; K = D_; base_blk = 0;    nblk = 256; }
        else if (blk < 768)  { src = Wh0; dst = g_Wh0p; K = H_; base_blk = 256;  nblk = 512; }
        else if (blk < 1280) { src = Wi1; dst = g_Wi1p; K = H_; base_blk = 768;  nblk = 512; }
        else                 { src = Wh1; dst = g_Wh1p; K = H_; base_blk = 1280; nblk = 512; }
        int K4 = K >> 2;
        int total = G_ * K4;
        for (int id = (blk - base_blk) * 256 + tid; id < total; id += nblk * 256) {
            int r = id / K4, k4 = (id - r * K4) * 4;
            int sr = (r & 3) * H_ + (r >> 2);
            float4 v = *(const float4*)&src[(size_t)sr * K + k4];
            __half2 a = {__float2half_rn(v.x), __float2half_rn(v.y)};
            __half2 b = {__float2half_rn(v.z), __float2half_rn(v.w)};
            *(uint2*)&dst[(size_t)r * K + k4] = make_uint2(*(uint32_t*)&a, *(uint32_t*)&b);
        }
    } else if (blk < 2816) {
        int total = TB_ * (D_ >> 2);
        for (int id = (blk - 1792) * 256 + tid; id < total; id += 1024 * 256) {
            int r = id / (D_ >> 2), k4 = (id - r * (D_ >> 2)) * 4;
            float4 v = *(const float4*)&input[(size_t)r * D_ + k4];
            __half2 a = {__float2half_rn(v.x), __float2half_rn(v.y)};
            __half2 b = {__float2half_rn(v.z), __float2half_rn(v.w)};
            *(uint2*)&g_Xp[(size_t)r * D_ + k4] = make_uint2(*(uint32_t*)&a, *(uint32_t*)&b);
        }
    } else if (blk < 2832) {
        int r = (blk - 2816) * 256 + tid;
        if (r < 128) g_g0_done[r] = 0u;
        if (r < G_) {
            int sr = (r & 3) * H_ + (r >> 2);
            g_b0[r] = bi0[sr] + bh0[sr];
            g_b1[r] = bi1[sr] + bh1[sr];
        }
    } else {
        for (int id = (blk - 2832) * 256 + tid; id < 2 * B_ * H_; id += 16 * 256) {
            int l = id / (B_ * H_);
            int b = (id / H_) % B_;
            int j = id % H_;
            float hv = h0[(b * 2 + l) * H_ + j];
            g_c0s[id] = c0[(b * 2 + l) * H_ + j];
            f16 hh = __float2half_rn(hv);
            if (l == 0) g_h0p[0][b * H_ + j] = hh;
            else        g_h1p[0][b * H_ + j] = hh;
        }
    }
}

// ---------------- G0-role body (512 threads, 16 warps 4x4) ----------------
#define GAS 72
__device__ void g0_body(int gid, char* smraw)
{
    f16* sm = (f16*)smraw;
    const int AS = 128 * GAS;
    f16* sA = sm;
    f16* sB = sm + 3 * AS;
    uint32_t sA_u = (uint32_t)__cvta_generic_to_shared(sA);
    uint32_t sB_u = (uint32_t)__cvta_generic_to_shared(sB);

    const f16 *A = g_Xp, *B = g_Wi0p;
    const int K = 512;
    int by = gid >> 5, bx = gid & 31;
    int m0 = by * 128, n0 = bx * 128;

    int tid = threadIdx.x, w = tid >> 5, lane = tid & 31, g = lane >> 2, t4 = lane & 3;
    int wm = w & 3, wn = w >> 2;     // 4 x 4 warp grid, warp tile 32x32
    const int NC = K / 64;

    int lr = lane & 15;
    int lcA = (lane >> 4) * 8;
    uint32_t aBase[2], bBase[2];
#pragma unroll
    for (int mt = 0; mt < 2; mt++)
        aBase[mt] = (uint32_t)(((wm * 32 + mt * 16 + lr) * GAS + lcA) * 2);
#pragma unroll
    for (int p = 0; p < 2; p++)
        bBase[p] = (uint32_t)(((wn * 32 + p * 16 + (lane & 7) + ((lane >> 4) & 1) * 8) * GAS
                               + ((lane >> 3) & 1) * 8) * 2);

    float acc[2][4][4];
#pragma unroll
    for (int a = 0; a < 2; a++)
#pragma unroll
        for (int b = 0; b < 4; b++)
#pragma unroll
            for (int c = 0; c < 4; c++) acc[a][b][c] = 0.f;

    auto issue = [&](int c) {
        int k0 = c * 64;
        int st = c % 3;
#pragma unroll
        for (int v = 0; v < 2; v++) {
            int idx = tid + v * NT_;
            int r = idx >> 3, s = idx & 7;
            cp_async16(&sA[st * AS + r * GAS + s * 8], &A[(size_t)(m0 + r) * K + k0 + s * 8]);
        }
#pragma unroll
        for (int v = 0; v < 2; v++) {
            int idx = tid + v * NT_;
            int r = idx >> 3, s = idx & 7;
            cp_async16(&sB[st * AS + r * GAS + s * 8], &B[(size_t)(n0 + r) * K + k0 + s * 8]);
        }
        cp_commit();
    };

    issue(0); issue(1);
    for (int c = 0; c < NC; c++) {
        if (c + 1 < NC) cp_wait<1>(); else cp_wait<0>();
        __syncthreads();
        if (c + 2 < NC) issue(c + 2);
        uint32_t stA = sA_u + (uint32_t)((c % 3) * AS * 2);
        uint32_t stB = sB_u + (uint32_t)((c % 3) * AS * 2);
#pragma unroll
        for (int kk = 0; kk < 4; kk++) {
            uint32_t kbb = (uint32_t)(kk * 32);
            uint32_t Aa[2][4], Bh[4][2];
#pragma unroll
            for (int mt = 0; mt < 2; mt++)
                ldsm4(Aa[mt][0], Aa[mt][1], Aa[mt][2], Aa[mt][3], stA + aBase[mt] + kbb);
#pragma unroll
            for (int p = 0; p < 2; p++)
                ldsm4(Bh[2 * p][0], Bh[2 * p][1], Bh[2 * p + 1][0], Bh[2 * p + 1][1],
                      stB + bBase[p] + kbb);
#pragma unroll
            for (int mt = 0; mt < 2; mt++)
#pragma unroll
                for (int nt = 0; nt < 4; nt++)
                    mma16816(acc[mt][nt], Aa[mt][0], Aa[mt][1], Aa[mt][2], Aa[mt][3], Bh[nt][0], Bh[nt][1]);
        }
    }

#pragma unroll
    for (int mt = 0; mt < 2; mt++)
#pragma unroll
        for (int nt = 0; nt < 4; nt++) {
            int row = m0 + wm * 32 + mt * 16 + g;
            int col = n0 + wn * 32 + nt * 8 + 2 * t4;
            float ba = g_b0[col], bb = g_b0[col + 1];
            *(float2*)&g_G0[(size_t)row * G_ + col] =
                make_float2(acc[mt][nt][0] + ba, acc[mt][nt][1] + bb);
            *(float2*)&g_G0[(size_t)(row + 8) * G_ + col] =
                make_float2(acc[mt][nt][2] + ba, acc[mt][nt][3] + bb);
        }

    __threadfence();
    __syncthreads();
    if (tid == 0) atomicAdd(&g_g0_done[by], 1u);
}

// ---------------- merged-role body (wavefront, 512 threads wm2 x wn4 x wk2) ----------------
#define WSTR 1032
#define ASTR 136
#define ASTG (64 * ASTR)
#define BSTG (32 * ASTR)
#define ZBANK (64 * 36)
#define MERGED_SMEM ((64 * WSTR + 3 * ASTG + 3 * BSTG) * 2 + 2 * ZBANK * 4)   // 228864 B

__device__ void merged_body(int rbid, const int* __restrict__ reset,
                            float* __restrict__ out, char* smraw)
{
    f16* smem = (f16*)smraw;
    f16* sW0 = smem;
    f16* sW1 = smem + 32 * WSTR;
    f16* sA  = smem + 64 * WSTR;
    f16* sB  = sA + 3 * ASTG;
    float* zs = (float*)(sB + 3 * BSTG);
    uint32_t sW0_u = (uint32_t)__cvta_generic_to_shared(sW0);
    uint32_t sW1_u = (uint32_t)__cvta_generic_to_shared(sW1);
    uint32_t sA_u  = (uint32_t)__cvta_generic_to_shared(sA);
    uint32_t sB_u  = (uint32_t)__cvta_generic_to_shared(sB);

    int tid = threadIdx.x, w = tid >> 5, lane = tid & 31, g = lane >> 2, t4 = lane & 3;
    int wk = w & 1, wn = (w >> 1) & 3, wm = w >> 3;
    int n0 = rbid * 32;
    unsigned gen0 = ld_acq(&g_bar_gen);

    for (int i = tid; i < 32 * 128; i += NT_) {
        int r = i >> 7, sseg = i & 127;
        *(uint4*)&sW0[r * WSTR + sseg * 8] = *(const uint4*)&g_Wh0p[(size_t)(n0 + r) * H_ + sseg * 8];
        *(uint4*)&sW1[r * WSTR + sseg * 8] = *(const uint4*)&g_Wh1p[(size_t)(n0 + r) * H_ + sseg * 8];
    }

    int lr = lane & 15;
    int lcA = (lane >> 4) * 8;
    uint32_t aBase[2];
    aBase[0] = (uint32_t)(((wm * 32 + 0 + lr) * ASTR + lcA) * 2);
    aBase[1] = (uint32_t)(((wm * 32 + 16 + lr) * ASTR + lcA) * 2);
    // single n8 tile per warp
    uint32_t wBase = (uint32_t)(((wn * 8 + (lane & 7)) * WSTR
                                 + ((lane >> 3) & 1) * 8 + ((lane >> 4) & 1) * 16) * 2);
    uint32_t bBaseS = (uint32_t)(((wn * 8 + (lane & 7)) * ASTR
                                  + ((lane >> 3) & 1) * 8 + ((lane >> 4) & 1) * 16) * 2);

    int bb = tid >> 3, jl = tid & 7, j = rbid * 8 + jl;
    int wrow[4] = { wm * 32 + g, wm * 32 + 8 + g, wm * 32 + 16 + g, wm * 32 + 24 + g };

    float c0r = g_c0s[(0 * B_ + bb) * H_ + j];
    float c1r = g_c0s[(1 * B_ + bb) * H_ + j];

    float4 b1v = *(const float4*)&g_b1[n0 + 4 * jl];

    float rst0, rst1, kw[4];
    rst0 = (float)reset[bb];
    rst1 = 0.f;
    kw[0] = kw[1] = kw[2] = kw[3] = 1.f;

    if (tid == 0) { while (ld_acq(&g_g0_done[0]) < 32u) { } }
    __syncthreads();
    float4 gp = __ldcs((const float4*)&g_G0[(size_t)bb * G_ + n0 + 4 * jl]);

    unsigned grp = (unsigned)rbid >> 4;

    for (int s = 0; s <= T_; s++) {
        const f16* A0 = g_h0p[s & 1];          // h0_{s-1}
        const f16* A1 = g_h1p[(s + 1) & 1];    // h1_{s-2}

        float acc0[2][4], accWi[2][4];
#pragma unroll
        for (int a = 0; a < 2; a++)
#pragma unroll
            for (int c = 0; c < 4; c++) { acc0[a][c] = 0.f; accWi[a][c] = 0.f; }

        auto issueF = [&](int c) {
            int k0 = c * 128, st = c % 3;
#pragma unroll
            for (int v = 0; v < 2; v++) {
                int idx = tid + v * NT_;
                int r = idx >> 4, sseg = idx & 15;
                cp_async16(&sA[st * ASTG + r * ASTR + sseg * 8], &A0[(size_t)r * H_ + k0 + sseg * 8]);
            }
            {
                int r = tid >> 4, sseg = tid & 15;
                cp_async16(&sB[st * BSTG + r * ASTR + sseg * 8],
                           &g_Wi1p[(size_t)(n0 + r) * H_ + k0 + sseg * 8]);
            }
            cp_commit();
        };
        auto issueH = [&](int c) {
            int k0 = c * 128, st = c % 3;
#pragma unroll
            for (int v = 0; v < 2; v++) {
                int idx = tid + v * NT_;
                int r = idx >> 4, sseg = idx & 15;
                cp_async16(&sA[st * ASTG + r * ASTR + sseg * 8], &A1[(size_t)r * H_ + k0 + sseg * 8]);
            }
            cp_commit();
        };

        // ---- loop1: acc0 (Wh0) + accWi (Wi1), A = h0_{s-1} ----
        issueF(0); issueF(1);
        for (int c = 0; c < 8; c++) {
            if (c + 1 < 8) cp_wait<1>(); else cp_wait<0>();
            __syncthreads();
            if (c + 2 < 8) issueF(c + 2);
            else if (c == 7 && s >= 1) issueH(0);
            uint32_t stA = sA_u + (uint32_t)((c % 3) * ASTG * 2);
            uint32_t stB = sB_u + (uint32_t)((c % 3) * BSTG * 2);
            uint32_t wOffC = (uint32_t)(c * 128 * 2);
#pragma unroll
            for (int kpi = 0; kpi < 2; kpi++) {
                int kp = kpi * 2 + wk;
                uint32_t kpb = (uint32_t)(kp * 64);
                uint32_t Bq0[4], BqW[4];
                ldsm4(Bq0[0], Bq0[1], Bq0[2], Bq0[3], sW0_u + wBase + wOffC + kpb);
                ldsm4(BqW[0], BqW[1], BqW[2], BqW[3], stB + bBaseS + kpb);
#pragma unroll
                for (int h = 0; h < 2; h++) {
                    uint32_t kbb = kpb + (uint32_t)(h * 32);
                    uint32_t Aa[2][4];
#pragma unroll
                    for (int mt = 0; mt < 2; mt++)
                        ldsm4(Aa[mt][0], Aa[mt][1], Aa[mt][2], Aa[mt][3], stA + aBase[mt] + kbb);
#pragma unroll
                    for (int mt = 0; mt < 2; mt++) {
                        mma16816(acc0[mt],  Aa[mt][0], Aa[mt][1], Aa[mt][2], Aa[mt][3],
                                 Bq0[h * 2], Bq0[h * 2 + 1]);
                        mma16816(accWi[mt], Aa[mt][0], Aa[mt][1], Aa[mt][2], Aa[mt][3],
                                 BqW[h * 2], BqW[h * 2 + 1]);
                    }
                }
            }
        }

        // layer0 partials -> zs
        {
            float* zb = zs + wk * ZBANK;
            int c0 = wn * 8 + 2 * t4;
#pragma unroll
            for (int mt = 0; mt < 2; mt++) {
                int r0 = wm * 32 + mt * 16 + g;
                zb[r0 * 36 + c0]     = acc0[mt][0];
                zb[r0 * 36 + c0 + 1] = acc0[mt][1];
                zb[(r0 + 8) * 36 + c0]     = acc0[mt][2];
                zb[(r0 + 8) * 36 + c0 + 1] = acc0[mt][3];
            }
        }
        __syncthreads();

        if (s >= 1) issueH(1);

        // tail0: layer0 activation, store h0_s  (one item per thread)
        if (s < T_) {
            float keep = 1.0f - rst0;
            int zi_i = bb * 36 + 4 * jl;
            float zi = gp.x + keep * (zs[zi_i + 0] + zs[ZBANK + zi_i + 0]);
            float zf = gp.y + keep * (zs[zi_i + 1] + zs[ZBANK + zi_i + 1]);
            float zg = gp.z + keep * (zs[zi_i + 2] + zs[ZBANK + zi_i + 2]);
            float zo = gp.w + keep * (zs[zi_i + 3] + zs[ZBANK + zi_i + 3]);
            float cn = sigmoidf_(zf) * keep * c0r + sigmoidf_(zi) * tanhf_(zg);
            float hn = sigmoidf_(zo) * tanhf_(cn);
            c0r = cn;
            g_h0p[(s + 1) & 1][bb * H_ + j] = __float2half_rn(hn);
            if (s == T_ - 1) {
                out[OUTS_ + (bb * 2 + 0) * H_ + j] = hn;
                out[OUTS_ + 2 * B_ * H_ + (bb * 2 + 0) * H_ + j] = cn;
            }
        }

        float hn_s, cn_s;
        if (s >= 1) {
            // ---- loop2: accWh (Wh1), A = h1_{s-2} ----
            float accWh[2][4];
#pragma unroll
            for (int a = 0; a < 2; a++)
#pragma unroll
                for (int c = 0; c < 4; c++) accWh[a][c] = 0.f;

            for (int c = 0; c < 8; c++) {
                if (c + 1 < 8) cp_wait<1>(); else cp_wait<0>();
                __syncthreads();
                if (c + 2 < 8) issueH(c + 2);
                uint32_t stA = sA_u + (uint32_t)((c % 3) * ASTG * 2);
                uint32_t wOffC = (uint32_t)(c * 128 * 2);
#pragma unroll
                for (int kpi = 0; kpi < 2; kpi++) {
                    int kp = kpi * 2 + wk;
                    uint32_t kpb = (uint32_t)(kp * 64);
                    uint32_t Bq1[4];
                    ldsm4(Bq1[0], Bq1[1], Bq1[2], Bq1[3], sW1_u + wBase + wOffC + kpb);
#pragma unroll
                    for (int h = 0; h < 2; h++) {
                        uint32_t kbb = kpb + (uint32_t)(h * 32);
                        uint32_t Aa[2][4];
#pragma unroll
                        for (int mt = 0; mt < 2; mt++)
                            ldsm4(Aa[mt][0], Aa[mt][1], Aa[mt][2], Aa[mt][3], stA + aBase[mt] + kbb);
#pragma unroll
                        for (int mt = 0; mt < 2; mt++)
                            mma16816(accWh[mt], Aa[mt][0], Aa[mt][1], Aa[mt][2], Aa[mt][3],
                                     Bq1[h * 2], Bq1[h * 2 + 1]);
                    }
                }
            }

            {
                float* zb = zs + wk * ZBANK;
                int c0 = wn * 8 + 2 * t4;
#pragma unroll
                for (int mt = 0; mt < 2; mt++) {
                    int r0 = wm * 32 + mt * 16 + g;
                    float k0f = kw[mt * 2 + 0], k1f = kw[mt * 2 + 1];
                    zb[r0 * 36 + c0]     = k0f * accWh[mt][0] + accWi[mt][0];
                    zb[r0 * 36 + c0 + 1] = k0f * accWh[mt][1] + accWi[mt][1];
                    zb[(r0 + 8) * 36 + c0]     = k1f * accWh[mt][2] + accWi[mt][2];
                    zb[(r0 + 8) * 36 + c0 + 1] = k1f * accWh[mt][3] + accWi[mt][3];
                }
            }
            __syncthreads();

            // tail1: layer1 activation, store h1_{s-1}
            {
                float keep = 1.0f - rst1;
                int zi_i = bb * 36 + 4 * jl;
                float zi = b1v.x + (zs[zi_i + 0] + zs[ZBANK + zi_i + 0]);
                float zf = b1v.y + (zs[zi_i + 1] + zs[ZBANK + zi_i + 1]);
                float zg = b1v.z + (zs[zi_i + 2] + zs[ZBANK + zi_i + 2]);
                float zo = b1v.w + (zs[zi_i + 3] + zs[ZBANK + zi_i + 3]);
                float cn = sigmoidf_(zf) * keep * c1r + sigmoidf_(zi) * tanhf_(zg);
                float hn = sigmoidf_(zo) * tanhf_(cn);
                c1r = cn; cn_s = cn; hn_s = hn;
                g_h1p[s & 1][bb * H_ + j] = __float2half_rn(hn);
                if (s == T_) {
                    out[OUTS_ + (bb * 2 + 1) * H_ + j] = hn;
                    out[OUTS_ + 2 * B_ * H_ + (bb * 2 + 1) * H_ + j] = cn;
                }
            }
        }

        // barrier arrive
        __syncthreads();
        if (tid == 0) {
            __threadfence();
            if (atomicAdd(&g_bar_grp[grp], 1u) == 15u) {
                g_bar_grp[grp] = 0u;
                if (atomicAdd(&g_bar_root, 1u) == 7u) {
                    g_bar_root = 0u;
                    __threadfence();
                    g_bar_gen = gen0 + s + 1;
                }
            }
        }

        // overlap: output stores + reset/kw prefetch
        if (s >= 1) {
            int t1 = s - 1;
            __stcs(&out[(size_t)t1 * B_ * H_ + bb * H_ + j], hn_s);
        }
        if (s + 1 <= T_) {
            rst1 = rst0;
            if (s + 1 < T_) rst0 = (float)reset[(s + 1) * B_ + bb];
#pragma unroll
            for (int i = 0; i < 4; i++)
                kw[i] = 1.0f - (float)reset[s * B_ + wrow[i]];
        }

        // barrier wait + G0-producer gate
        if (tid == 0) {
            while (ld_acq(&g_bar_gen) < gen0 + s + 1) { }
            if (s + 1 < T_) {
                unsigned by2 = (unsigned)(s + 1) >> 1;
                while (ld_acq(&g_g0_done[by2]) < 32u) { }
            }
        }
        __syncthreads();

        if (s + 1 < T_)
            gp = __ldcs((const float4*)&g_G0[((size_t)(s + 1) * B_ + bb) * G_ + n0 + 4 * jl]);
    }
}

// ---------------- fused kernel ----------------
__global__ __launch_bounds__(NT_, 1) void fused_kernel(const int* __restrict__ reset,
                                                       float* __restrict__ out)
{
    extern __shared__ char smraw[];
    int bid = blockIdx.x;
    if (bid < NB_) merged_body(bid, reset, out, smraw);
    else           g0_body(bid - NB_, smraw);
}

// ---------------- launch ----------------
extern "C" void kernel_launch(void* const* d_in, const int* in_sizes, int n_in,
                              void* d_out, int out_size)
{
    (void)in_sizes; (void)n_in; (void)out_size;
    const float* input = (const float*)d_in[0];
    const int*   reset = (const int*)d_in[1];
    const float* h0    = (const float*)d_in[2];
    const float* c0    = (const float*)d_in[3];
    const float* Wi0   = (const float*)d_in[4];
    const float* Wh0   = (const float*)d_in[5];
    const float* bi0   = (const float*)d_in[6];
    const float* bh0   = (const float*)d_in[7];
    const float* Wi1   = (const float*)d_in[8];
    const float* Wh1   = (const float*)d_in[9];
    const float* bi1   = (const float*)d_in[10];
    const float* bh1   = (const float*)d_in[11];
    float* out = (float*)d_out;

    cudaFuncSetAttribute(fused_kernel, cudaFuncAttributeMaxDynamicSharedMemorySize, MERGED_SMEM);

    setup_kernel<<<2848, 256>>>(input, h0, c0, Wi0, Wh0, bi0, bh0, Wi1, Wh1, bi1, bh1);
    fused_kernel<<<NB_ + G0B_, NT_, MERGED_SMEM>>>(reset, out);
}

// round 16
// speedup vs baseline: 1.1428x; 1.0854x over previous
#include <cuda_runtime.h>
#include <cuda_fp16.h>
#include <cstdint>
#include <cstddef>

typedef __half f16;

#define T_ 256
#define B_ 64
#define D_ 512
#define H_ 1024
#define G_ 4096
#define TB_ (T_ * B_)
#define OUTS_ (TB_ * H_)
#define NB_ 128          // merged-role CTAs (scheduled first)
#define G0B_ 4096        // G0-role CTAs

// ---------------- device scratch ----------------
__device__ f16   g_Xp  [(size_t)TB_ * D_];
__device__ f16   g_Wi0p[(size_t)G_  * D_];
__device__ f16   g_Wh0p[(size_t)G_  * H_];
__device__ f16   g_Wi1p[(size_t)G_  * H_];
__device__ f16   g_Wh1p[(size_t)G_  * H_];
__device__ float g_b0[G_], g_b1[G_];
__device__ float g_G0[(size_t)TB_ * G_];
__device__ float g_c0s[2 * B_ * H_];
__device__ f16   g_h0p[2][B_ * H_];
__device__ f16   g_h1p[2][B_ * H_];
__device__ unsigned g_bar_grp[8];
__device__ unsigned g_bar_root;
__device__ unsigned g_bar_gen;       // monotonic across replays
__device__ unsigned g_g0_done[128];  // cleared in setup

// ---------------- helpers ----------------
__device__ __forceinline__ void cp_async16(void* sdst, const void* gsrc) {
    uint32_t s = (uint32_t)__cvta_generic_to_shared(sdst);
    asm volatile("cp.async.cg.shared.global [%0], [%1], 16;\n" :: "r"(s), "l"(gsrc));
}
__device__ __forceinline__ void cp_commit() { asm volatile("cp.async.commit_group;\n"); }
template <int N> __device__ __forceinline__ void cp_wait() {
    asm volatile("cp.async.wait_group %0;\n" :: "n"(N));
}
__device__ __forceinline__ unsigned ld_acq(const unsigned* p) {
    unsigned v; asm volatile("ld.acquire.gpu.u32 %0, [%1];" : "=r"(v) : "l"(p)); return v;
}
__device__ __forceinline__ void mma16816(float* d,
    uint32_t a0, uint32_t a1, uint32_t a2, uint32_t a3, uint32_t b0, uint32_t b1)
{
    asm volatile(
        "mma.sync.aligned.m16n8k16.row.col.f32.f16.f16.f32 "
        "{%0,%1,%2,%3},{%4,%5,%6,%7},{%8,%9},{%0,%1,%2,%3};\n"
        : "+f"(d[0]), "+f"(d[1]), "+f"(d[2]), "+f"(d[3])
        : "r"(a0), "r"(a1), "r"(a2), "r"(a3), "r"(b0), "r"(b1));
}
__device__ __forceinline__ void ldsm4(uint32_t& a, uint32_t& b, uint32_t& c, uint32_t& d,
                                      uint32_t addr)
{
    asm volatile("ldmatrix.sync.aligned.m8n8.x4.shared.b16 {%0,%1,%2,%3}, [%4];"
        : "=r"(a), "=r"(b), "=r"(c), "=r"(d) : "r"(addr));
}
__device__ __forceinline__ float sigmoidf_(float z) {
    return __fdividef(1.f, 1.f + __expf(-z));
}
__device__ __forceinline__ float tanhf_(float z) {
    return __fdividef(2.f, 1.f + __expf(-2.f * z)) - 1.f;
}

// ---------------- unified setup kernel ----------------
__global__ void setup_kernel(const float* __restrict__ input,
                             const float* __restrict__ h0, const float* __restrict__ c0,
                             const float* __restrict__ Wi0, const float* __restrict__ Wh0,
                             const float* __restrict__ bi0, const float* __restrict__ bh0,
                             const float* __restrict__ Wi1, const float* __restrict__ Wh1,
                             const float* __restrict__ bi1, const float* __restrict__ bh1)
{
    int blk = blockIdx.x;
    int tid = threadIdx.x;

    if (blk < 1792) {
        const float* src; f16* dst; int K, base_blk, nblk;
        if (blk < 256)       { src = Wi0; dst = g_Wi0p; K = D_; base_blk = 0;    nblk = 256; }
        else if (blk < 768)  { src = Wh0; dst = g_Wh0p; K = H_; base_blk = 256;  nblk = 512; }
        else if (blk < 1280) { src = Wi1; dst = g_Wi1p; K = H_; base_blk = 768;  nblk = 512; }
        else                 { src = Wh1; dst = g_Wh1p; K = H_; base_blk = 1280; nblk = 512; }
        int K4 = K >> 2;
        int total = G_ * K4;
        for (int id = (blk - base_blk) * 256 + tid; id < total; id += nblk * 256) {
            int r = id / K4, k4 = (id - r * K4) * 4;
            int sr = (r & 3) * H_ + (r >> 2);
            float4 v = *(const float4*)&src[(size_t)sr * K + k4];
            __half2 a = {__float2half_rn(v.x), __float2half_rn(v.y)};
            __half2 b = {__float2half_rn(v.z), __float2half_rn(v.w)};
            *(uint2*)&dst[(size_t)r * K + k4] = make_uint2(*(uint32_t*)&a, *(uint32_t*)&b);
        }
    } else if (blk < 2816) {
        int total = TB_ * (D_ >> 2);
        for (int id = (blk - 1792) * 256 + tid; id < total; id += 1024 * 256) {
            int r = id / (D_ >> 2), k4 = (id - r * (D_ >> 2)) * 4;
            float4 v = *(const float4*)&input[(size_t)r * D_ + k4];
            __half2 a = {__float2half_rn(v.x), __float2half_rn(v.y)};
            __half2 b = {__float2half_rn(v.z), __float2half_rn(v.w)};
            *(uint2*)&g_Xp[(size_t)r * D_ + k4] = make_uint2(*(uint32_t*)&a, *(uint32_t*)&b);
        }
    } else if (blk < 2832) {
        int r = (blk - 2816) * 256 + tid;
        if (r < 128) g_g0_done[r] = 0u;
        if (r < G_) {
            int sr = (r & 3) * H_ + (r >> 2);
            g_b0[r] = bi0[sr] + bh0[sr];
            g_b1[r] = bi1[sr] + bh1[sr];
        }
    } else {
        for (int id = (blk - 2832) * 256 + tid; id < 2 * B_ * H_; id += 16 * 256) {
            int l = id / (B_ * H_);
            int b = (id / H_) % B_;
            int j = id % H_;
            float hv = h0[(b * 2 + l) * H_ + j];
            g_c0s[id] = c0[(b * 2 + l) * H_ + j];
            f16 hh = __float2half_rn(hv);
            if (l == 0) g_h0p[0][b * H_ + j] = hh;
            else        g_h1p[0][b * H_ + j] = hh;
        }
    }
}

// ---------------- G0-role body ----------------
#define GAS 72
__device__ void g0_body(int gid, char* smraw)
{
    f16* sm = (f16*)smraw;
    const int AS = 128 * GAS;
    f16* sA = sm;
    f16* sB = sm + 3 * AS;
    uint32_t sA_u = (uint32_t)__cvta_generic_to_shared(sA);
    uint32_t sB_u = (uint32_t)__cvta_generic_to_shared(sB);

    const f16 *A = g_Xp, *B = g_Wi0p;
    const int K = 512;
    int by = gid >> 5, bx = gid & 31;
    int m0 = by * 128, n0 = bx * 128;

    int tid = threadIdx.x, w = tid >> 5, lane = tid & 31, g = lane >> 2, t4 = lane & 3;
    int wm = w & 1, wn = w >> 1;
    const int NC = K / 64;

    int lr = lane & 15;
    int lcA = (lane >> 4) * 8;
    uint32_t aBase[4], bBase[2];
#pragma unroll
    for (int mt = 0; mt < 4; mt++)
        aBase[mt] = (uint32_t)(((wm * 64 + mt * 16 + lr) * GAS + lcA) * 2);
#pragma unroll
    for (int p = 0; p < 2; p++)
        bBase[p] = (uint32_t)(((wn * 32 + p * 16 + (lane & 7) + ((lane >> 4) & 1) * 8) * GAS
                               + ((lane >> 3) & 1) * 8) * 2);

    float acc[4][4][4];
#pragma unroll
    for (int a = 0; a < 4; a++)
#pragma unroll
        for (int b = 0; b < 4; b++)
#pragma unroll
            for (int c = 0; c < 4; c++) acc[a][b][c] = 0.f;

    auto issue = [&](int c) {
        int k0 = c * 64;
        int st = c % 3;
#pragma unroll
        for (int v = 0; v < 4; v++) {
            int idx = tid + v * 256;
            int r = idx >> 3, s = idx & 7;
            cp_async16(&sA[st * AS + r * GAS + s * 8], &A[(size_t)(m0 + r) * K + k0 + s * 8]);
        }
#pragma unroll
        for (int v = 0; v < 4; v++) {
            int idx = tid + v * 256;
            int r = idx >> 3, s = idx & 7;
            cp_async16(&sB[st * AS + r * GAS + s * 8], &B[(size_t)(n0 + r) * K + k0 + s * 8]);
        }
        cp_commit();
    };

    issue(0); issue(1);
    for (int c = 0; c < NC; c++) {
        if (c + 1 < NC) cp_wait<1>(); else cp_wait<0>();
        __syncthreads();
        if (c + 2 < NC) issue(c + 2);
        uint32_t stA = sA_u + (uint32_t)((c % 3) * AS * 2);
        uint32_t stB = sB_u + (uint32_t)((c % 3) * AS * 2);
#pragma unroll
        for (int kk = 0; kk < 4; kk++) {
            uint32_t kbb = (uint32_t)(kk * 32);
            uint32_t Aa[4][4], Bh[4][2];
#pragma unroll
            for (int mt = 0; mt < 4; mt++)
                ldsm4(Aa[mt][0], Aa[mt][1], Aa[mt][2], Aa[mt][3], stA + aBase[mt] + kbb);
#pragma unroll
            for (int p = 0; p < 2; p++)
                ldsm4(Bh[2 * p][0], Bh[2 * p][1], Bh[2 * p + 1][0], Bh[2 * p + 1][1],
                      stB + bBase[p] + kbb);
#pragma unroll
            for (int mt = 0; mt < 4; mt++)
#pragma unroll
                for (int nt = 0; nt < 4; nt++)
                    mma16816(acc[mt][nt], Aa[mt][0], Aa[mt][1], Aa[mt][2], Aa[mt][3], Bh[nt][0], Bh[nt][1]);
        }
    }

#pragma unroll
    for (int mt = 0; mt < 4; mt++)
#pragma unroll
        for (int nt = 0; nt < 4; nt++) {
            int row = m0 + wm * 64 + mt * 16 + g;
            int col = n0 + wn * 32 + nt * 8 + 2 * t4;
            float ba = g_b0[col], bb = g_b0[col + 1];
            *(float2*)&g_G0[(size_t)row * G_ + col] =
                make_float2(acc[mt][nt][0] + ba, acc[mt][nt][1] + bb);
            *(float2*)&g_G0[(size_t)(row + 8) * G_ + col] =
                make_float2(acc[mt][nt][2] + ba, acc[mt][nt][3] + bb);
        }

    __threadfence();
    __syncthreads();
    if (tid == 0) atomicAdd(&g_g0_done[by], 1u);
}

// ---------------- merged-role body (wavefront, R13 configuration) ----------------
#define WSTR 1032
#define ASTR 136
#define ASTG (64 * ASTR)
#define BSTG (32 * ASTR)
#define ZBANK (64 * 36)
#define MERGED_SMEM ((64 * WSTR + 3 * ASTG + 3 * BSTG) * 2 + 2 * ZBANK * 4)   // 228864 B

__device__ void merged_body(int rbid, const int* __restrict__ reset,
                            float* __restrict__ out, char* smraw)
{
    f16* smem = (f16*)smraw;
    f16* sW0 = smem;
    f16* sW1 = smem + 32 * WSTR;
    f16* sA  = smem + 64 * WSTR;
    f16* sB  = sA + 3 * ASTG;
    float* zs = (float*)(sB + 3 * BSTG);
    uint32_t sW0_u = (uint32_t)__cvta_generic_to_shared(sW0);
    uint32_t sW1_u = (uint32_t)__cvta_generic_to_shared(sW1);
    uint32_t sA_u  = (uint32_t)__cvta_generic_to_shared(sA);
    uint32_t sB_u  = (uint32_t)__cvta_generic_to_shared(sB);

    int tid = threadIdx.x, w = tid >> 5, lane = tid & 31, g = lane >> 2, t4 = lane & 3;
    int wk = w & 1, wn = (w >> 1) & 1, wm = w >> 2;
    int n0 = rbid * 32;
    unsigned gen0 = ld_acq(&g_bar_gen);

    for (int i = tid; i < 32 * 128; i += 256) {
        int r = i >> 7, sseg = i & 127;
        *(uint4*)&sW0[r * WSTR + sseg * 8] = *(const uint4*)&g_Wh0p[(size_t)(n0 + r) * H_ + sseg * 8];
        *(uint4*)&sW1[r * WSTR + sseg * 8] = *(const uint4*)&g_Wh1p[(size_t)(n0 + r) * H_ + sseg * 8];
    }

    int lr = lane & 15;
    int lcA = (lane >> 4) * 8;
    uint32_t aBase[2];
    aBase[0] = (uint32_t)(((wm * 32 + 0 + lr) * ASTR + lcA) * 2);
    aBase[1] = (uint32_t)(((wm * 32 + 16 + lr) * ASTR + lcA) * 2);
    uint32_t wBase[2], bBaseS[2];
#pragma unroll
    for (int nt = 0; nt < 2; nt++) {
        wBase[nt]  = (uint32_t)(((wn * 16 + nt * 8 + (lane & 7)) * WSTR
                                 + ((lane >> 3) & 1) * 8 + ((lane >> 4) & 1) * 16) * 2);
        bBaseS[nt] = (uint32_t)(((wn * 16 + nt * 8 + (lane & 7)) * ASTR
                                 + ((lane >> 3) & 1) * 8 + ((lane >> 4) & 1) * 16) * 2);
    }

    int bb = tid >> 3, jl = tid & 7, j = rbid * 8 + jl;
    int bb2 = (tid + 256) >> 3;
    int wrow[4] = { wm * 32 + g, wm * 32 + 8 + g, wm * 32 + 16 + g, wm * 32 + 24 + g };

    float c0r[2], c1r[2];
    c0r[0] = g_c0s[(0 * B_ + bb) * H_ + j];
    c0r[1] = g_c0s[(0 * B_ + bb2) * H_ + j];
    c1r[0] = g_c0s[(1 * B_ + bb) * H_ + j];
    c1r[1] = g_c0s[(1 * B_ + bb2) * H_ + j];

    float4 b1v = *(const float4*)&g_b1[n0 + 4 * jl];

    float rst0[2], rst1[2], kw[4];
    rst0[0] = (float)__ldg(&reset[bb]);
    rst0[1] = (float)__ldg(&reset[bb2]);
    rst1[0] = rst1[1] = 0.f;
    kw[0] = kw[1] = kw[2] = kw[3] = 1.f;

    if (tid == 0) { while (ld_acq(&g_g0_done[0]) < 32u) { } }
    __syncthreads();
    float4 gp[2];
    gp[0] = __ldcs((const float4*)&g_G0[(size_t)bb * G_ + n0 + 4 * jl]);
    gp[1] = __ldcs((const float4*)&g_G0[(size_t)bb2 * G_ + n0 + 4 * jl]);

    unsigned grp = (unsigned)rbid >> 4;

    for (int s = 0; s <= T_; s++) {
        const f16* A0 = g_h0p[s & 1];          // h0_{s-1}
        const f16* A1 = g_h1p[(s + 1) & 1];    // h1_{s-2}

        float acc0[2][2][4], accWi[2][2][4];
#pragma unroll
        for (int a = 0; a < 2; a++)
#pragma unroll
            for (int b = 0; b < 2; b++)
#pragma unroll
                for (int c = 0; c < 4; c++) { acc0[a][b][c] = 0.f; accWi[a][b][c] = 0.f; }

        auto issueF = [&](int c) {
            int k0 = c * 128, st = c % 3;
#pragma unroll
            for (int v = 0; v < 4; v++) {
                int idx = tid + v * 256;
                int r = idx >> 4, sseg = idx & 15;
                cp_async16(&sA[st * ASTG + r * ASTR + sseg * 8], &A0[(size_t)r * H_ + k0 + sseg * 8]);
            }
#pragma unroll
            for (int v = 0; v < 2; v++) {
                int idx = tid + v * 256;
                int r = idx >> 4, sseg = idx & 15;
                cp_async16(&sB[st * BSTG + r * ASTR + sseg * 8],
                           &g_Wi1p[(size_t)(n0 + r) * H_ + k0 + sseg * 8]);
            }
            cp_commit();
        };
        auto issueH = [&](int c) {
            int k0 = c * 128, st = c % 3;
#pragma unroll
            for (int v = 0; v < 4; v++) {
                int idx = tid + v * 256;
                int r = idx >> 4, sseg = idx & 15;
                cp_async16(&sA[st * ASTG + r * ASTR + sseg * 8], &A1[(size_t)r * H_ + k0 + sseg * 8]);
            }
            cp_commit();
        };

        issueF(0); issueF(1);
        for (int c = 0; c < 8; c++) {
            if (c + 1 < 8) cp_wait<1>(); else cp_wait<0>();
            __syncthreads();
            if (c + 2 < 8) issueF(c + 2);
            else if (c == 7 && s >= 1) issueH(0);
            uint32_t stA = sA_u + (uint32_t)((c % 3) * ASTG * 2);
            uint32_t stB = sB_u + (uint32_t)((c % 3) * BSTG * 2);
            uint32_t wOffC = (uint32_t)(c * 128 * 2);
#pragma unroll
            for (int kpi = 0; kpi < 2; kpi++) {
                int kp = kpi * 2 + wk;
                uint32_t kpb = (uint32_t)(kp * 64);
                uint32_t Bq0[2][4], BqW[2][4];
#pragma unroll
                for (int nt = 0; nt < 2; nt++) {
                    ldsm4(Bq0[nt][0], Bq0[nt][1], Bq0[nt][2], Bq0[nt][3],
                          sW0_u + wBase[nt] + wOffC + kpb);
                    ldsm4(BqW[nt][0], BqW[nt][1], BqW[nt][2], BqW[nt][3],
                          stB + bBaseS[nt] + kpb);
                }
#pragma unroll
                for (int h = 0; h < 2; h++) {
                    uint32_t kbb = kpb + (uint32_t)(h * 32);
                    uint32_t Aa[2][4];
#pragma unroll
                    for (int mt = 0; mt < 2; mt++)
                        ldsm4(Aa[mt][0], Aa[mt][1], Aa[mt][2], Aa[mt][3], stA + aBase[mt] + kbb);
#pragma unroll
                    for (int mt = 0; mt < 2; mt++)
#pragma unroll
                        for (int nt = 0; nt < 2; nt++) {
                            mma16816(acc0[mt][nt], Aa[mt][0], Aa[mt][1], Aa[mt][2], Aa[mt][3],
                                     Bq0[nt][h * 2], Bq0[nt][h * 2 + 1]);
                            mma16816(accWi[mt][nt], Aa[mt][0], Aa[mt][1], Aa[mt][2], Aa[mt][3],
                                     BqW[nt][h * 2], BqW[nt][h * 2 + 1]);
                        }
                }
            }
        }

        // layer0 partials -> zs
        {
            float* zb = zs + wk * ZBANK;
#pragma unroll
            for (int mt = 0; mt < 2; mt++)
#pragma unroll
                for (int nt = 0; nt < 2; nt++) {
                    int r0 = wm * 32 + mt * 16 + g;
                    int c0 = wn * 16 + nt * 8 + 2 * t4;
                    zb[r0 * 36 + c0]     = acc0[mt][nt][0];
                    zb[r0 * 36 + c0 + 1] = acc0[mt][nt][1];
                    zb[(r0 + 8) * 36 + c0]     = acc0[mt][nt][2];
                    zb[(r0 + 8) * 36 + c0 + 1] = acc0[mt][nt][3];
                }
        }
        __syncthreads();

        if (s >= 1) issueH(1);

        // tail0
        if (s < T_) {
#pragma unroll
            for (int it = 0; it < 2; it++) {
                int b = it ? bb2 : bb;
                float keep = 1.0f - rst0[it];
                int zi_i = b * 36 + 4 * jl;
                float zi = gp[it].x + keep * (zs[zi_i + 0] + zs[ZBANK + zi_i + 0]);
                float zf = gp[it].y + keep * (zs[zi_i + 1] + zs[ZBANK + zi_i + 1]);
                float zg = gp[it].z + keep * (zs[zi_i + 2] + zs[ZBANK + zi_i + 2]);
                float zo = gp[it].w + keep * (zs[zi_i + 3] + zs[ZBANK + zi_i + 3]);
                float cn = sigmoidf_(zf) * keep * c0r[it] + sigmoidf_(zi) * tanhf_(zg);
                float hn = sigmoidf_(zo) * tanhf_(cn);
                c0r[it] = cn;
                g_h0p[(s + 1) & 1][b * H_ + j] = __float2half_rn(hn);
                if (s == T_ - 1) {
                    __stcs(&out[OUTS_ + (b * 2 + 0) * H_ + j], hn);
                    __stcs(&out[OUTS_ + 2 * B_ * H_ + (b * 2 + 0) * H_ + j], cn);
                }
            }
        }

        float hn_s[2], cn_s[2];
        if (s >= 1) {
            float accWh[2][2][4];
#pragma unroll
            for (int a = 0; a < 2; a++)
#pragma unroll
                for (int b = 0; b < 2; b++)
#pragma unroll
                    for (int c = 0; c < 4; c++) accWh[a][b][c] = 0.f;

            for (int c = 0; c < 8; c++) {
                if (c + 1 < 8) cp_wait<1>(); else cp_wait<0>();
                __syncthreads();
                if (c + 2 < 8) issueH(c + 2);
                uint32_t stA = sA_u + (uint32_t)((c % 3) * ASTG * 2);
                uint32_t wOffC = (uint32_t)(c * 128 * 2);
#pragma unroll
                for (int kpi = 0; kpi < 2; kpi++) {
                    int kp = kpi * 2 + wk;
                    uint32_t kpb = (uint32_t)(kp * 64);
                    uint32_t Bq1[2][4];
#pragma unroll
                    for (int nt = 0; nt < 2; nt++)
                        ldsm4(Bq1[nt][0], Bq1[nt][1], Bq1[nt][2], Bq1[nt][3],
                              sW1_u + wBase[nt] + wOffC + kpb);
#pragma unroll
                    for (int h = 0; h < 2; h++) {
                        uint32_t kbb = kpb + (uint32_t)(h * 32);
                        uint32_t Aa[2][4];
#pragma unroll
                        for (int mt = 0; mt < 2; mt++)
                            ldsm4(Aa[mt][0], Aa[mt][1], Aa[mt][2], Aa[mt][3], stA + aBase[mt] + kbb);
#pragma unroll
                        for (int mt = 0; mt < 2; mt++)
#pragma unroll
                            for (int nt = 0; nt < 2; nt++)
                                mma16816(accWh[mt][nt], Aa[mt][0], Aa[mt][1], Aa[mt][2], Aa[mt][3],
                                         Bq1[nt][h * 2], Bq1[nt][h * 2 + 1]);
                    }
                }
            }

            {
                float* zb = zs + wk * ZBANK;
#pragma unroll
                for (int mt = 0; mt < 2; mt++)
#pragma unroll
                    for (int nt = 0; nt < 2; nt++) {
                        int r0 = wm * 32 + mt * 16 + g;
                        int c0 = wn * 16 + nt * 8 + 2 * t4;
                        float k0f = kw[mt * 2 + 0], k1f = kw[mt * 2 + 1];
                        zb[r0 * 36 + c0]     = k0f * accWh[mt][nt][0] + accWi[mt][nt][0];
                        zb[r0 * 36 + c0 + 1] = k0f * accWh[mt][nt][1] + accWi[mt][nt][1];
                        zb[(r0 + 8) * 36 + c0]     = k1f * accWh[mt][nt][2] + accWi[mt][nt][2];
                        zb[(r0 + 8) * 36 + c0 + 1] = k1f * accWh[mt][nt][3] + accWi[mt][nt][3];
                    }
            }
            __syncthreads();

            // tail1
#pragma unroll
            for (int it = 0; it < 2; it++) {
                int b = it ? bb2 : bb;
                float keep = 1.0f - rst1[it];
                int zi_i = b * 36 + 4 * jl;
                float zi = b1v.x + (zs[zi_i + 0] + zs[ZBANK + zi_i + 0]);
                float zf = b1v.y + (zs[zi_i + 1] + zs[ZBANK + zi_i + 1]);
                float zg = b1v.z + (zs[zi_i + 2] + zs[ZBANK + zi_i + 2]);
                float zo = b1v.w + (zs[zi_i + 3] + zs[ZBANK + zi_i + 3]);
                float cn = sigmoidf_(zf) * keep * c1r[it] + sigmoidf_(zi) * tanhf_(zg);
                float hn = sigmoidf_(zo) * tanhf_(cn);
                c1r[it] = cn; cn_s[it] = cn; hn_s[it] = hn;
                g_h1p[s & 1][b * H_ + j] = __float2half_rn(hn);
                if (s == T_) {
                    __stcs(&out[OUTS_ + (b * 2 + 1) * H_ + j], hn);
                    __stcs(&out[OUTS_ + 2 * B_ * H_ + (b * 2 + 1) * H_ + j], cn);
                }
            }
        }

        // barrier arrive
        __syncthreads();
        if (tid == 0) {
            __threadfence();
            if (atomicAdd(&g_bar_grp[grp], 1u) == 15u) {
                g_bar_grp[grp] = 0u;
                if (atomicAdd(&g_bar_root, 1u) == 7u) {
                    g_bar_root = 0u;
                    __threadfence();
                    g_bar_gen = gen0 + s + 1;
                }
            }
        }

        // overlap: output stores + reset/kw prefetch
        if (s >= 1) {
            int t1 = s - 1;
#pragma unroll
            for (int it = 0; it < 2; it++) {
                int b = it ? bb2 : bb;
                __stcs(&out[(size_t)t1 * B_ * H_ + b * H_ + j], hn_s[it]);
            }
        }
        if (s + 1 <= T_) {
            rst1[0] = rst0[0]; rst1[1] = rst0[1];
            if (s + 1 < T_) {
                rst0[0] = (float)__ldg(&reset[(s + 1) * B_ + bb]);
                rst0[1] = (float)__ldg(&reset[(s + 1) * B_ + bb2]);
            }
#pragma unroll
            for (int i = 0; i < 4; i++)
                kw[i] = 1.0f - (float)__ldg(&reset[s * B_ + wrow[i]]);
        }

        // barrier wait + G0-producer gate
        if (tid == 0) {
            while (ld_acq(&g_bar_gen) < gen0 + s + 1) { }
            if (s + 1 < T_) {
                unsigned by2 = (unsigned)(s + 1) >> 1;
                while (ld_acq(&g_g0_done[by2]) < 32u) { }
            }
        }
        __syncthreads();

        if (s + 1 < T_) {
            gp[0] = __ldcs((const float4*)&g_G0[((size_t)(s + 1) * B_ + bb) * G_ + n0 + 4 * jl]);
            gp[1] = __ldcs((const float4*)&g_G0[((size_t)(s + 1) * B_ + bb2) * G_ + n0 + 4 * jl]);
        }
    }
}

// ---------------- fused kernel ----------------
__global__ __launch_bounds__(256, 1) void fused_kernel(const int* __restrict__ reset,
                                                       float* __restrict__ out)
{
    extern __shared__ char smraw[];
    int bid = blockIdx.x;
    if (bid < NB_) merged_body(bid, reset, out, smraw);
    else           g0_body(bid - NB_, smraw);
}

// ---------------- launch ----------------
extern "C" void kernel_launch(void* const* d_in, const int* in_sizes, int n_in,
                              void* d_out, int out_size)
{
    (void)in_sizes; (void)n_in; (void)out_size;
    const float* input = (const float*)d_in[0];
    const int*   reset = (const int*)d_in[1];
    const float* h0    = (const float*)d_in[2];
    const float* c0    = (const float*)d_in[3];
    const float* Wi0   = (const float*)d_in[4];
    const float* Wh0   = (const float*)d_in[5];
    const float* bi0   = (const float*)d_in[6];
    const float* bh0   = (const float*)d_in[7];
    const float* Wi1   = (const float*)d_in[8];
    const float* Wh1   = (const float*)d_in[9];
    const float* bi1   = (const float*)d_in[10];
    const float* bh1   = (const float*)d_in[11];
    float* out = (float*)d_out;

    cudaFuncSetAttribute(fused_kernel, cudaFuncAttributeMaxDynamicSharedMemorySize, MERGED_SMEM);

    setup_kernel<<<2848, 256>>>(input, h0, c0, Wi0, Wh0, bi0, bh0, Wi1, Wh1, bi1, bh1);
    fused_kernel<<<NB_ + G0B_, 256, MERGED_SMEM>>>(reset, out);
}